// round 1
// baseline (speedup 1.0000x reference)
#include <cuda_runtime.h>
#include <math.h>

// ---------------- Problem constants ----------------
#define NN    16384
#define DD    256
#define HH    8
#define HDIM  32
#define EE    131072
#define II    682

// ---------------- Scratch (device globals; no allocations allowed) -------
__device__ float g_q   [NN * DD];        // query proj
__device__ float g_kv  [NN * 2 * DD];    // kv proj (interleaved k/v)
__device__ float g_qkv [NN * 3 * DD];    // qkv proj (interleaved q/k/v)
__device__ float g_expsc[EE * HH];       // exp(score) per edge/head
__device__ float g_ssum [NN * HH];       // softmax denominators per dst/head
__device__ float g_agg  [NN * DD];       // attention aggregation per dst
__device__ float g_tmp  [NN * DD];       // post-wout buffer
__device__ float g_x1   [NN * DD];       // after ntr block
__device__ float g_x2   [NN * DD];       // after rtr block
__device__ float g_h1   [NN * II];       // swiglu gate
__device__ float g_h2   [NN * II];       // swiglu value

// ---------------- SGEMM: C[M,Nc] = A[M,K] @ B[K,Nc], fp32, row-major -----
#define BM 64
#define BN 64
#define BK 16
__global__ __launch_bounds__(256) void sgemm_kernel(
    const float* __restrict__ A, const float* __restrict__ B,
    float* __restrict__ C, int M, int Nc, int K)
{
    __shared__ float As[BK][BM + 1];   // +1 pad: conflict-free transposed store
    __shared__ float Bs[BK][BN];

    const int tid = threadIdx.x;
    const int tx  = tid & 15;          // 0..15 -> 4 cols each
    const int ty  = tid >> 4;          // 0..15 -> 4 rows each
    const int row0 = blockIdx.y * BM;
    const int col0 = blockIdx.x * BN;

    float acc[4][4] = {};

    for (int kk = 0; kk < K; kk += BK) {
        // load A tile 64x16 (store transposed)
        #pragma unroll
        for (int i = 0; i < 4; i++) {
            int idx = tid + i * 256;       // 0..1023
            int m = idx >> 4, k = idx & 15;
            int gr = row0 + m, gk = kk + k;
            float v = 0.f;
            if (gr < M && gk < K) v = A[(long)gr * K + gk];
            As[k][m] = v;
        }
        // load B tile 16x64 (coalesced)
        #pragma unroll
        for (int i = 0; i < 4; i++) {
            int idx = tid + i * 256;
            int n = idx & 63, k = idx >> 6;
            int gn = col0 + n, gk = kk + k;
            float v = 0.f;
            if (gk < K && gn < Nc) v = B[(long)gk * Nc + gn];
            Bs[k][n] = v;
        }
        __syncthreads();

        #pragma unroll
        for (int k = 0; k < BK; k++) {
            float a[4], b[4];
            #pragma unroll
            for (int i = 0; i < 4; i++) a[i] = As[k][ty * 4 + i];
            #pragma unroll
            for (int j = 0; j < 4; j++) b[j] = Bs[k][tx * 4 + j];
            #pragma unroll
            for (int i = 0; i < 4; i++)
                #pragma unroll
                for (int j = 0; j < 4; j++)
                    acc[i][j] = fmaf(a[i], b[j], acc[i][j]);
        }
        __syncthreads();
    }

    #pragma unroll
    for (int i = 0; i < 4; i++) {
        int r = row0 + ty * 4 + i;
        if (r >= M) continue;
        #pragma unroll
        for (int j = 0; j < 4; j++) {
            int c = col0 + tx * 4 + j;
            if (c < Nc) C[(long)r * Nc + c] = acc[i][j];
        }
    }
}

// ---------------- zero accumulators (ssum + agg) ----------------
__global__ void zero_accum_kernel(int n_agg)
{
    int i = blockIdx.x * blockDim.x + threadIdx.x;
    if (i < NN * HH) g_ssum[i] = 0.f;
    if (i < n_agg)   g_agg[i]  = 0.f;
}

// ---------------- edge scores: cross attention ----------------
// q: [N, H*HD]; kv: [N, H*HD*2] interleaved (k at 2*d, v at 2*d+1)
__global__ void edge_scores_cross_kernel(
    const float* __restrict__ q, const float* __restrict__ kv,
    const int* __restrict__ eidx, int E, float scale)
{
    int warp = (blockIdx.x * blockDim.x + threadIdx.x) >> 5;
    int lane = threadIdx.x & 31;
    if (warp >= E) return;
    int src = eidx[warp];
    int dst = eidx[E + warp];
    int h  = lane >> 2;
    int d0 = lane & 3;
    const float* qr  = q  + (long)dst * DD  + h * HDIM;
    const float* kvr = kv + (long)src * 2*DD + h * 2*HDIM;
    float acc = 0.f;
    #pragma unroll
    for (int i = 0; i < 8; i++) {
        int d = d0 + i * 4;
        acc = fmaf(qr[d], kvr[2 * d], acc);
    }
    acc += __shfl_down_sync(0xffffffffu, acc, 2);
    acc += __shfl_down_sync(0xffffffffu, acc, 1);
    if (d0 == 0) {
        float sc = expf(acc * scale);
        g_expsc[(long)warp * HH + h] = sc;
        atomicAdd(&g_ssum[(long)dst * HH + h], sc);
    }
}

// ---------------- edge scores: self attention (with edge_attr, no scale) --
// qkv: [N, H*HD*3] interleaved (q at 3*d, k at 3*d+1, v at 3*d+2)
__global__ void edge_scores_self_kernel(
    const float* __restrict__ qkv, const float* __restrict__ attr,
    const int* __restrict__ eidx, int E)
{
    int warp = (blockIdx.x * blockDim.x + threadIdx.x) >> 5;
    int lane = threadIdx.x & 31;
    if (warp >= E) return;
    int src = eidx[warp];
    int dst = eidx[E + warp];
    int h  = lane >> 2;
    int d0 = lane & 3;
    const float* qr = qkv + (long)dst * 3*DD + h * 3*HDIM;
    const float* kr = qkv + (long)src * 3*DD + h * 3*HDIM;
    const float* ar = attr + (long)warp * DD + h * HDIM;
    float acc = 0.f;
    #pragma unroll
    for (int i = 0; i < 8; i++) {
        int d = d0 + i * 4;
        acc = fmaf(qr[3 * d] * kr[3 * d + 1], ar[d], acc);
    }
    acc += __shfl_down_sync(0xffffffffu, acc, 2);
    acc += __shfl_down_sync(0xffffffffu, acc, 1);
    if (d0 == 0) {
        float sc = expf(acc);
        g_expsc[(long)warp * HH + h] = sc;
        atomicAdd(&g_ssum[(long)dst * HH + h], sc);
    }
}

// ---------------- edge aggregation: cross (v from interleaved kv) ---------
__global__ void edge_agg_cross_kernel(
    const float* __restrict__ kv, const int* __restrict__ eidx, int E)
{
    int warp = (blockIdx.x * blockDim.x + threadIdx.x) >> 5;
    int lane = threadIdx.x & 31;
    if (warp >= E) return;
    int src = eidx[warp];
    int dst = eidx[E + warp];
    float w = 0.f;
    if (lane < HH)
        w = g_expsc[(long)warp * HH + lane] / g_ssum[(long)dst * HH + lane];
    #pragma unroll
    for (int h = 0; h < HH; h++) {
        float wh = __shfl_sync(0xffffffffu, w, h);
        float v = kv[(long)src * 2*DD + h * 2*HDIM + 2 * lane + 1];
        atomicAdd(&g_agg[(long)dst * DD + h * HDIM + lane], wh * v);
    }
}

// ---------------- edge aggregation: self (v from interleaved qkv) ---------
__global__ void edge_agg_self_kernel(
    const float* __restrict__ qkv, const int* __restrict__ eidx, int E)
{
    int warp = (blockIdx.x * blockDim.x + threadIdx.x) >> 5;
    int lane = threadIdx.x & 31;
    if (warp >= E) return;
    int src = eidx[warp];
    int dst = eidx[E + warp];
    float w = 0.f;
    if (lane < HH)
        w = g_expsc[(long)warp * HH + lane] / g_ssum[(long)dst * HH + lane];
    #pragma unroll
    for (int h = 0; h < HH; h++) {
        float wh = __shfl_sync(0xffffffffu, w, h);
        float v = qkv[(long)src * 3*DD + h * 3*HDIM + 3 * lane + 2];
        atomicAdd(&g_agg[(long)dst * DD + h * HDIM + lane], wh * v);
    }
}

// ---------------- residual + RMS norm (one block per row, D=256) ----------
__global__ void add_rmsnorm_kernel(
    const float* __restrict__ a, const float* __restrict__ b,
    const float* __restrict__ g, float* __restrict__ out, int N)
{
    int row = blockIdx.x;
    int t = threadIdx.x;
    if (row >= N) return;
    float x = a[(long)row * DD + t] + b[(long)row * DD + t];
    float ss = x * x;
    #pragma unroll
    for (int o = 16; o > 0; o >>= 1) ss += __shfl_xor_sync(0xffffffffu, ss, o);
    __shared__ float sh[8];
    __shared__ float stot;
    if ((t & 31) == 0) sh[t >> 5] = ss;
    __syncthreads();
    if (t == 0) {
        float s = 0.f;
        #pragma unroll
        for (int i = 0; i < 8; i++) s += sh[i];
        stot = s;
    }
    __syncthreads();
    float norm = sqrtf(stot * (1.0f / DD));
    float denom = fmaxf(norm, 1e-8f);
    out[(long)row * DD + t] = x / denom * g[t];
}

// ---------------- SwiGLU elementwise: h1 = h1*sigmoid(h1)*h2 ----------
__global__ void swiglu_mul_kernel(float* __restrict__ h1,
                                  const float* __restrict__ h2, long n)
{
    long i = (long)blockIdx.x * blockDim.x + threadIdx.x;
    if (i >= n) return;
    float h = h1[i];
    float sig = 1.0f / (1.0f + expf(-h));
    h1[i] = h * sig * h2[i];
}

// ---------------- host launcher ----------------
static inline void run_gemm(const float* A, const float* B, float* C,
                            int M, int Nc, int K)
{
    dim3 grid((Nc + BN - 1) / BN, (M + BM - 1) / BM);
    sgemm_kernel<<<grid, 256>>>(A, B, C, M, Nc, K);
}

extern "C" void kernel_launch(void* const* d_in, const int* in_sizes, int n_in,
                              void* d_out, int out_size)
{
    const float* root   = (const float*)d_in[0];
    const float* node   = (const float*)d_in[1];
    const float* fringe = (const float*)d_in[2];
    const int* ntr_idx  = (const int*)d_in[3];
    const int* rtr_idx  = (const int*)d_in[4];
    const int* rtf_idx  = (const int*)d_in[5];
    const float* edge_attr = (const float*)d_in[6];
    const float* ntr_wq  = (const float*)d_in[7];
    const float* ntr_wkv = (const float*)d_in[8];
    const float* ntr_wout= (const float*)d_in[9];
    const float* ntr_g   = (const float*)d_in[10];
    const float* rtr_wqkv= (const float*)d_in[11];
    const float* rtr_wout= (const float*)d_in[12];
    const float* rtr_g   = (const float*)d_in[13];
    const float* ffn_win = (const float*)d_in[14];
    const float* ffn_v   = (const float*)d_in[15];
    const float* ffn_wout= (const float*)d_in[16];
    const float* ffn_g   = (const float*)d_in[17];
    const float* rtf_wq  = (const float*)d_in[18];
    const float* rtf_wkv = (const float*)d_in[19];
    const float* rtf_wout= (const float*)d_in[20];
    float* out = (float*)d_out;

    const int N = in_sizes[0] / DD;     // 16384
    const int E = in_sizes[3] / 2;      // 131072
    const int I = in_sizes[14] / DD;    // 682
    const float scale = 0.17677669529663689f;  // 1/sqrt(32)

    float *p_q, *p_kv, *p_qkv, *p_agg, *p_tmp, *p_x1, *p_x2, *p_h1, *p_h2;
    cudaGetSymbolAddress((void**)&p_q,   g_q);
    cudaGetSymbolAddress((void**)&p_kv,  g_kv);
    cudaGetSymbolAddress((void**)&p_qkv, g_qkv);
    cudaGetSymbolAddress((void**)&p_agg, g_agg);
    cudaGetSymbolAddress((void**)&p_tmp, g_tmp);
    cudaGetSymbolAddress((void**)&p_x1,  g_x1);
    cudaGetSymbolAddress((void**)&p_x2,  g_x2);
    cudaGetSymbolAddress((void**)&p_h1,  g_h1);
    cudaGetSymbolAddress((void**)&p_h2,  g_h2);

    const int edge_blocks = (E * 32 + 255) / 256;
    const int zero_blocks = (N * DD + 255) / 256;

    // ===== Stage 1: nodes_to_root CrossMHA + residual + RMSNorm -> x1 =====
    zero_accum_kernel<<<zero_blocks, 256>>>(N * DD);
    run_gemm(root, ntr_wq,  p_q,  N, DD,     DD);
    run_gemm(node, ntr_wkv, p_kv, N, 2 * DD, DD);
    edge_scores_cross_kernel<<<edge_blocks, 256>>>(p_q, p_kv, ntr_idx, E, scale);
    edge_agg_cross_kernel<<<edge_blocks, 256>>>(p_kv, ntr_idx, E);
    run_gemm(p_agg, ntr_wout, p_tmp, N, DD, DD);
    add_rmsnorm_kernel<<<N, 256>>>(root, p_tmp, ntr_g, p_x1, N);

    // ===== Stage 2: roots_to_root SelfMHA + residual + RMSNorm -> x2 =====
    zero_accum_kernel<<<zero_blocks, 256>>>(N * DD);
    run_gemm(p_x1, rtr_wqkv, p_qkv, N, 3 * DD, DD);
    edge_scores_self_kernel<<<edge_blocks, 256>>>(p_qkv, edge_attr, rtr_idx, E);
    edge_agg_self_kernel<<<edge_blocks, 256>>>(p_qkv, rtr_idx, E);
    run_gemm(p_agg, rtr_wout, p_tmp, N, DD, DD);
    add_rmsnorm_kernel<<<N, 256>>>(p_x1, p_tmp, rtr_g, p_x2, N);

    // ===== Stage 3: SwiGLU FFN (on root_features) + residual + RMSNorm ====
    run_gemm(root, ffn_win, p_h1, N, I, DD);
    run_gemm(root, ffn_v,   p_h2, N, I, DD);
    {
        long nel = (long)N * I;
        swiglu_mul_kernel<<<(int)((nel + 255) / 256), 256>>>(p_h1, p_h2, nel);
    }
    run_gemm(p_h1, ffn_wout, p_tmp, N, DD, I);
    add_rmsnorm_kernel<<<N, 256>>>(p_tmp, p_x2, ffn_g, out, N);   // out[0 : N*D)

    // ===== Stage 4: root_to_fringe CrossMHA -> out[N*D : 2*N*D) =====
    zero_accum_kernel<<<zero_blocks, 256>>>(N * DD);
    run_gemm(fringe, rtf_wq,  p_q,  N, DD,     DD);
    run_gemm(root,   rtf_wkv, p_kv, N, 2 * DD, DD);
    edge_scores_cross_kernel<<<edge_blocks, 256>>>(p_q, p_kv, rtf_idx, E, scale);
    edge_agg_cross_kernel<<<edge_blocks, 256>>>(p_kv, rtf_idx, E);
    run_gemm(p_agg, rtf_wout, out + (long)N * DD, N, DD, DD);
}

// round 4
// speedup vs baseline: 1.4976x; 1.4976x over previous
#include <cuda_runtime.h>
#include <math.h>

// ---------------- Problem constants ----------------
#define NN    16384
#define DD    256
#define HH    8
#define HDIM  32
#define EE    131072
#define II    682

// ---------------- Scratch (device globals; no allocations allowed) -------
__device__ float g_q   [NN * DD];
__device__ float g_kv  [NN * 2 * DD];
__device__ float g_qkv [NN * 3 * DD];
__device__ float g_expsc[EE * HH];
__device__ float g_ssum [NN * HH];
__device__ float g_agg  [NN * DD];
__device__ float g_tmp  [NN * DD];
__device__ float g_x1   [NN * DD];
__device__ float g_x2   [NN * DD];
__device__ float g_h1   [NN * II];
__device__ float g_h2   [NN * II];

// ============ TF32 tensor-core GEMM: C[M,Nc] = A[M,K] @ B[K,Nc] ============
// Tile 128x128x16. 256 threads = 8 warps in 2x4 (m,n); warp tile 64x32 via
// 4x4 m16n8k8 fragments. Smem padded for conflict-free fragment LDS.
#define TBM 128
#define TBN 128
#define TBK 16
#define AS_STRIDE 20
#define BS_STRIDE 136

__device__ __forceinline__ unsigned to_tf32_bits(float x) {
    unsigned y;
    asm("cvt.rna.tf32.f32 %0, %1;" : "=r"(y) : "f"(x));
    return y;
}

__global__ __launch_bounds__(256) void tf32_gemm_kernel(
    const float* __restrict__ A, const float* __restrict__ B,
    float* __restrict__ C, int M, int Nc, int K)
{
    __shared__ unsigned As[TBM][AS_STRIDE];   // [m][k] tf32 bits
    __shared__ unsigned Bs[TBK][BS_STRIDE];   // [k][n] tf32 bits

    const int tid  = threadIdx.x;
    const int lane = tid & 31;
    const int warp = tid >> 5;
    const int wm   = (warp >> 2) * 64;
    const int wn   = (warp & 3) * 32;
    const int g    = lane >> 2;            // 0..7
    const int t4   = lane & 3;             // 0..3

    const int row0 = blockIdx.y * TBM;
    const int col0 = blockIdx.x * TBN;

    float acc[4][4][4];
    #pragma unroll
    for (int i = 0; i < 4; i++)
        #pragma unroll
        for (int j = 0; j < 4; j++)
            #pragma unroll
            for (int r = 0; r < 4; r++) acc[i][j][r] = 0.f;

    for (int kk = 0; kk < K; kk += TBK) {
        // ---- load A tile [128][16] ----
        #pragma unroll
        for (int i = 0; i < 8; i++) {
            int idx = tid + i * 256;
            int m = idx >> 4, k = idx & 15;
            int gk = kk + k;
            float v = 0.f;
            if (gk < K) v = A[(long)(row0 + m) * K + gk];
            As[m][k] = to_tf32_bits(v);
        }
        // ---- load B tile [16][128] ----
        #pragma unroll
        for (int i = 0; i < 8; i++) {
            int idx = tid + i * 256;
            int n = idx & 127, k = idx >> 7;
            int gk = kk + k, gn = col0 + n;
            float v = 0.f;
            if (gk < K && gn < Nc) v = B[(long)gk * Nc + gn];
            Bs[k][n] = to_tf32_bits(v);
        }
        __syncthreads();

        #pragma unroll
        for (int ks = 0; ks < 2; ks++) {
            const int k0 = ks * 8;
            unsigned a[4][4], b[4][2];
            #pragma unroll
            for (int mi = 0; mi < 4; mi++) {
                int m = wm + mi * 16;
                a[mi][0] = As[m + g][k0 + t4];
                a[mi][1] = As[m + g + 8][k0 + t4];
                a[mi][2] = As[m + g][k0 + t4 + 4];
                a[mi][3] = As[m + g + 8][k0 + t4 + 4];
            }
            #pragma unroll
            for (int ni = 0; ni < 4; ni++) {
                int n = wn + ni * 8 + g;
                b[ni][0] = Bs[k0 + t4][n];
                b[ni][1] = Bs[k0 + t4 + 4][n];
            }
            #pragma unroll
            for (int mi = 0; mi < 4; mi++)
                #pragma unroll
                for (int ni = 0; ni < 4; ni++) {
                    asm volatile(
                        "mma.sync.aligned.m16n8k8.row.col.f32.tf32.tf32.f32 "
                        "{%0,%1,%2,%3}, {%4,%5,%6,%7}, {%8,%9}, {%0,%1,%2,%3};\n"
                        : "+f"(acc[mi][ni][0]), "+f"(acc[mi][ni][1]),
                          "+f"(acc[mi][ni][2]), "+f"(acc[mi][ni][3])
                        : "r"(a[mi][0]), "r"(a[mi][1]), "r"(a[mi][2]), "r"(a[mi][3]),
                          "r"(b[ni][0]), "r"(b[ni][1]));
                }
        }
        __syncthreads();
    }

    // ---- epilogue ----
    #pragma unroll
    for (int mi = 0; mi < 4; mi++) {
        #pragma unroll
        for (int ni = 0; ni < 4; ni++) {
            int r0 = row0 + wm + mi * 16 + g;
            int c  = col0 + wn + ni * 8 + 2 * t4;
            if (c + 1 < Nc) {
                *(float2*)&C[(long)r0 * Nc + c] =
                    make_float2(acc[mi][ni][0], acc[mi][ni][1]);
                *(float2*)&C[(long)(r0 + 8) * Nc + c] =
                    make_float2(acc[mi][ni][2], acc[mi][ni][3]);
            } else if (c < Nc) {
                C[(long)r0 * Nc + c]       = acc[mi][ni][0];
                C[(long)(r0 + 8) * Nc + c] = acc[mi][ni][2];
            }
        }
    }
}

// ---------------- zero accumulators (ssum + agg) ----------------
__global__ void zero_accum_kernel(int n_agg)
{
    int i = blockIdx.x * blockDim.x + threadIdx.x;
    if (i < NN * HH) g_ssum[i] = 0.f;
    if (i < n_agg)   g_agg[i]  = 0.f;
}

// ---------------- edge scores: cross attention ----------------
__global__ void edge_scores_cross_kernel(
    const float* __restrict__ q, const float* __restrict__ kv,
    const int* __restrict__ eidx, int E, float scale)
{
    int warp = (blockIdx.x * blockDim.x + threadIdx.x) >> 5;
    int lane = threadIdx.x & 31;
    if (warp >= E) return;
    int src = eidx[warp];
    int dst = eidx[E + warp];
    int h  = lane >> 2;
    int d0 = lane & 3;
    const float* qr  = q  + (long)dst * DD  + h * HDIM;
    const float* kvr = kv + (long)src * 2*DD + h * 2*HDIM;
    float acc = 0.f;
    #pragma unroll
    for (int i = 0; i < 8; i++) {
        int d = d0 + i * 4;
        acc = fmaf(qr[d], kvr[2 * d], acc);
    }
    acc += __shfl_down_sync(0xffffffffu, acc, 2);
    acc += __shfl_down_sync(0xffffffffu, acc, 1);
    if (d0 == 0) {
        float sc = expf(acc * scale);
        g_expsc[(long)warp * HH + h] = sc;
        atomicAdd(&g_ssum[(long)dst * HH + h], sc);
    }
}

// ---------------- edge scores: self attention ----------------
__global__ void edge_scores_self_kernel(
    const float* __restrict__ qkv, const float* __restrict__ attr,
    const int* __restrict__ eidx, int E)
{
    int warp = (blockIdx.x * blockDim.x + threadIdx.x) >> 5;
    int lane = threadIdx.x & 31;
    if (warp >= E) return;
    int src = eidx[warp];
    int dst = eidx[E + warp];
    int h  = lane >> 2;
    int d0 = lane & 3;
    const float* qr = qkv + (long)dst * 3*DD + h * 3*HDIM;
    const float* kr = qkv + (long)src * 3*DD + h * 3*HDIM;
    const float* ar = attr + (long)warp * DD + h * HDIM;
    float acc = 0.f;
    #pragma unroll
    for (int i = 0; i < 8; i++) {
        int d = d0 + i * 4;
        acc = fmaf(qr[3 * d] * kr[3 * d + 1], ar[d], acc);
    }
    acc += __shfl_down_sync(0xffffffffu, acc, 2);
    acc += __shfl_down_sync(0xffffffffu, acc, 1);
    if (d0 == 0) {
        float sc = expf(acc);
        g_expsc[(long)warp * HH + h] = sc;
        atomicAdd(&g_ssum[(long)dst * HH + h], sc);
    }
}

// ---------------- edge aggregation: cross ----------------
__global__ void edge_agg_cross_kernel(
    const float* __restrict__ kv, const int* __restrict__ eidx, int E)
{
    int warp = (blockIdx.x * blockDim.x + threadIdx.x) >> 5;
    int lane = threadIdx.x & 31;
    if (warp >= E) return;
    int src = eidx[warp];
    int dst = eidx[E + warp];
    float w = 0.f;
    if (lane < HH)
        w = g_expsc[(long)warp * HH + lane] / g_ssum[(long)dst * HH + lane];
    #pragma unroll
    for (int h = 0; h < HH; h++) {
        float wh = __shfl_sync(0xffffffffu, w, h);
        float v = kv[(long)src * 2*DD + h * 2*HDIM + 2 * lane + 1];
        atomicAdd(&g_agg[(long)dst * DD + h * HDIM + lane], wh * v);
    }
}

// ---------------- edge aggregation: self ----------------
__global__ void edge_agg_self_kernel(
    const float* __restrict__ qkv, const int* __restrict__ eidx, int E)
{
    int warp = (blockIdx.x * blockDim.x + threadIdx.x) >> 5;
    int lane = threadIdx.x & 31;
    if (warp >= E) return;
    int src = eidx[warp];
    int dst = eidx[E + warp];
    float w = 0.f;
    if (lane < HH)
        w = g_expsc[(long)warp * HH + lane] / g_ssum[(long)dst * HH + lane];
    #pragma unroll
    for (int h = 0; h < HH; h++) {
        float wh = __shfl_sync(0xffffffffu, w, h);
        float v = qkv[(long)src * 3*DD + h * 3*HDIM + 3 * lane + 2];
        atomicAdd(&g_agg[(long)dst * DD + h * HDIM + lane], wh * v);
    }
}

// ---------------- residual + RMS norm ----------------
__global__ void add_rmsnorm_kernel(
    const float* __restrict__ a, const float* __restrict__ b,
    const float* __restrict__ g, float* __restrict__ out, int N)
{
    int row = blockIdx.x;
    int t = threadIdx.x;
    if (row >= N) return;
    float x = a[(long)row * DD + t] + b[(long)row * DD + t];
    float ss = x * x;
    #pragma unroll
    for (int o = 16; o > 0; o >>= 1) ss += __shfl_xor_sync(0xffffffffu, ss, o);
    __shared__ float sh[8];
    __shared__ float stot;
    if ((t & 31) == 0) sh[t >> 5] = ss;
    __syncthreads();
    if (t == 0) {
        float s = 0.f;
        #pragma unroll
        for (int i = 0; i < 8; i++) s += sh[i];
        stot = s;
    }
    __syncthreads();
    float norm = sqrtf(stot * (1.0f / DD));
    float denom = fmaxf(norm, 1e-8f);
    out[(long)row * DD + t] = x / denom * g[t];
}

// ---------------- SwiGLU elementwise ----------------
__global__ void swiglu_mul_kernel(float* __restrict__ h1,
                                  const float* __restrict__ h2, long n)
{
    long i = (long)blockIdx.x * blockDim.x + threadIdx.x;
    if (i >= n) return;
    float h = h1[i];
    float sig = 1.0f / (1.0f + expf(-h));
    h1[i] = h * sig * h2[i];
}

// ---------------- host launcher ----------------
static inline void run_gemm(const float* A, const float* B, float* C,
                            int M, int Nc, int K)
{
    dim3 grid((Nc + TBN - 1) / TBN, (M + TBM - 1) / TBM);
    tf32_gemm_kernel<<<grid, 256>>>(A, B, C, M, Nc, K);
}

extern "C" void kernel_launch(void* const* d_in, const int* in_sizes, int n_in,
                              void* d_out, int out_size)
{
    const float* root   = (const float*)d_in[0];
    const float* node   = (const float*)d_in[1];
    const float* fringe = (const float*)d_in[2];
    const int* ntr_idx  = (const int*)d_in[3];
    const int* rtr_idx  = (const int*)d_in[4];
    const int* rtf_idx  = (const int*)d_in[5];
    const float* edge_attr = (const float*)d_in[6];
    const float* ntr_wq  = (const float*)d_in[7];
    const float* ntr_wkv = (const float*)d_in[8];
    const float* ntr_wout= (const float*)d_in[9];
    const float* ntr_g   = (const float*)d_in[10];
    const float* rtr_wqkv= (const float*)d_in[11];
    const float* rtr_wout= (const float*)d_in[12];
    const float* rtr_g   = (const float*)d_in[13];
    const float* ffn_win = (const float*)d_in[14];
    const float* ffn_v   = (const float*)d_in[15];
    const float* ffn_wout= (const float*)d_in[16];
    const float* ffn_g   = (const float*)d_in[17];
    const float* rtf_wq  = (const float*)d_in[18];
    const float* rtf_wkv = (const float*)d_in[19];
    const float* rtf_wout= (const float*)d_in[20];
    float* out = (float*)d_out;

    const int N = in_sizes[0] / DD;     // 16384
    const int E = in_sizes[3] / 2;      // 131072
    const int I = in_sizes[14] / DD;    // 682
    const float scale = 0.17677669529663689f;  // 1/sqrt(32)

    float *p_q, *p_kv, *p_qkv, *p_agg, *p_tmp, *p_x1, *p_x2, *p_h1, *p_h2;
    cudaGetSymbolAddress((void**)&p_q,   g_q);
    cudaGetSymbolAddress((void**)&p_kv,  g_kv);
    cudaGetSymbolAddress((void**)&p_qkv, g_qkv);
    cudaGetSymbolAddress((void**)&p_agg, g_agg);
    cudaGetSymbolAddress((void**)&p_tmp, g_tmp);
    cudaGetSymbolAddress((void**)&p_x1,  g_x1);
    cudaGetSymbolAddress((void**)&p_x2,  g_x2);
    cudaGetSymbolAddress((void**)&p_h1,  g_h1);
    cudaGetSymbolAddress((void**)&p_h2,  g_h2);

    const int edge_blocks = (E * 32 + 255) / 256;
    const int zero_blocks = (N * DD + 255) / 256;

    // ===== Stage 1: nodes_to_root CrossMHA + residual + RMSNorm -> x1 =====
    zero_accum_kernel<<<zero_blocks, 256>>>(N * DD);
    run_gemm(root, ntr_wq,  p_q,  N, DD,     DD);
    run_gemm(node, ntr_wkv, p_kv, N, 2 * DD, DD);
    edge_scores_cross_kernel<<<edge_blocks, 256>>>(p_q, p_kv, ntr_idx, E, scale);
    edge_agg_cross_kernel<<<edge_blocks, 256>>>(p_kv, ntr_idx, E);
    run_gemm(p_agg, ntr_wout, p_tmp, N, DD, DD);
    add_rmsnorm_kernel<<<N, 256>>>(root, p_tmp, ntr_g, p_x1, N);

    // ===== Stage 2: roots_to_root SelfMHA + residual + RMSNorm -> x2 =====
    zero_accum_kernel<<<zero_blocks, 256>>>(N * DD);
    run_gemm(p_x1, rtr_wqkv, p_qkv, N, 3 * DD, DD);
    edge_scores_self_kernel<<<edge_blocks, 256>>>(p_qkv, edge_attr, rtr_idx, E);
    edge_agg_self_kernel<<<edge_blocks, 256>>>(p_qkv, rtr_idx, E);
    run_gemm(p_agg, rtr_wout, p_tmp, N, DD, DD);
    add_rmsnorm_kernel<<<N, 256>>>(p_x1, p_tmp, rtr_g, p_x2, N);

    // ===== Stage 3: SwiGLU FFN + residual + RMSNorm -> out[0:N*D) =====
    run_gemm(root, ffn_win, p_h1, N, I, DD);
    run_gemm(root, ffn_v,   p_h2, N, I, DD);
    {
        long nel = (long)N * I;
        swiglu_mul_kernel<<<(int)((nel + 255) / 256), 256>>>(p_h1, p_h2, nel);
    }
    run_gemm(p_h1, ffn_wout, p_tmp, N, DD, I);
    add_rmsnorm_kernel<<<N, 256>>>(p_tmp, p_x2, ffn_g, out, N);

    // ===== Stage 4: root_to_fringe CrossMHA -> out[N*D : 2*N*D) =====
    zero_accum_kernel<<<zero_blocks, 256>>>(N * DD);
    run_gemm(fringe, rtf_wq,  p_q,  N, DD,     DD);
    run_gemm(root,   rtf_wkv, p_kv, N, 2 * DD, DD);
    edge_scores_cross_kernel<<<edge_blocks, 256>>>(p_q, p_kv, rtf_idx, E, scale);
    edge_agg_cross_kernel<<<edge_blocks, 256>>>(p_kv, rtf_idx, E);
    run_gemm(p_agg, rtf_wout, out + (long)N * DD, N, DD, DD);
}

// round 5
// speedup vs baseline: 1.9515x; 1.3031x over previous
#include <cuda_runtime.h>
#include <math.h>

// ---------------- Problem constants ----------------
#define NN    16384
#define DD    256
#define HH    8
#define HDIM  32
#define EE    131072
#define II    682
#define ILD   688      // padded leading dim for swiglu intermediates (16B-aligned rows)

// ---------------- Scratch (device globals) ----------------
__device__ float g_q   [NN * DD];
__device__ float g_kv  [NN * 2 * DD];
__device__ float g_qkv [NN * 3 * DD];
__device__ float g_ssum[NN * HH];
__device__ float g_agg [NN * DD];
__device__ float g_tmp [NN * DD];
__device__ float g_x1  [NN * DD];
__device__ float g_x2  [NN * DD];
__device__ float g_h1  [NN * ILD];
__device__ float g_h2  [NN * ILD];

// ============ Pipelined TF32 GEMM: C[M,Nc] = A[M,K] @ B[K,Nc] ============
// 64x128x16 tile, 2-stage cp.async double buffer, 8 warps (2x4), warp 32x32.
#define TBM 64
#define TBN 128
#define TBK 16
#define ASTR 20     // (20g + t) % 32 distinct -> conflict-free A frags
#define BSTR 136    // (8t + g) % 32 distinct  -> conflict-free B frags

__device__ __forceinline__ unsigned to_tf32_bits(float x) {
    unsigned y;
    asm("cvt.rna.tf32.f32 %0, %1;" : "=r"(y) : "f"(x));
    return y;
}
__device__ __forceinline__ void cpa16(float* dst, const float* src, int ss) {
    unsigned d = (unsigned)__cvta_generic_to_shared(dst);
    asm volatile("cp.async.ca.shared.global [%0], [%1], 16, %2;\n"
                 :: "r"(d), "l"(src), "r"(ss));
}
__device__ __forceinline__ void cpa4(float* dst, const float* src, int ss) {
    unsigned d = (unsigned)__cvta_generic_to_shared(dst);
    asm volatile("cp.async.ca.shared.global [%0], [%1], 4, %2;\n"
                 :: "r"(d), "l"(src), "r"(ss));
}

__global__ __launch_bounds__(256) void tf32_gemm_pipe(
    const float* __restrict__ A, int lda,
    const float* __restrict__ B, int ldb,
    float* __restrict__ C, int ldc,
    int M, int Nc, int K)
{
    __shared__ float As[2][TBM * ASTR];
    __shared__ float Bs[2][TBK * BSTR];

    const int tid  = threadIdx.x;
    const int lane = tid & 31;
    const int warp = tid >> 5;
    const int wm   = (warp >> 2) * 32;
    const int wn   = (warp & 3) * 32;
    const int g    = lane >> 2;          // 0..7
    const int t4   = lane & 3;           // 0..3
    const int row0 = blockIdx.y * TBM;
    const int col0 = blockIdx.x * TBN;
    const bool bvec = ((ldb & 3) == 0) && ((Nc & 3) == 0);

    float acc[2][4][4];
    #pragma unroll
    for (int i = 0; i < 2; i++)
        #pragma unroll
        for (int j = 0; j < 4; j++)
            #pragma unroll
            for (int r = 0; r < 4; r++) acc[i][j][r] = 0.f;

    const int ntiles = (K + TBK - 1) / TBK;

    auto load_stage = [&](int s, int kk) {
        // A tile: 64x16 floats = 256 float4; one per thread
        {
            int m = tid >> 2, kq = tid & 3;
            int gk = kk + kq * 4;
            int ss = (K - gk) * 4; ss = ss < 0 ? 0 : (ss > 16 ? 16 : ss);
            cpa16(&As[s][m * ASTR + kq * 4],
                  A + (long)(row0 + m) * lda + gk, ss);
        }
        if (bvec) {
            // B tile: 16x128 floats = 512 float4; two per thread
            #pragma unroll
            for (int i = 0; i < 2; i++) {
                int idx = tid + i * 256;
                int k = idx >> 5, nq = idx & 31;
                int gk = kk + k, gn = col0 + nq * 4;
                int ss = 0;
                if (gk < K) { ss = (Nc - gn) * 4; ss = ss < 0 ? 0 : (ss > 16 ? 16 : ss); }
                cpa16(&Bs[s][k * BSTR + nq * 4],
                      B + (long)gk * ldb + gn, ss);
            }
        } else {
            // scalar path (misaligned ldb / odd Nc): 2048 scalars, 8 per thread
            #pragma unroll
            for (int i = 0; i < 8; i++) {
                int idx = tid + i * 256;
                int k = idx >> 7, n = idx & 127;
                int gk = kk + k, gn = col0 + n;
                int ss = (gk < K && gn < Nc) ? 4 : 0;
                cpa4(&Bs[s][k * BSTR + n],
                     B + (long)gk * ldb + gn, ss);
            }
        }
    };

    load_stage(0, 0);
    asm volatile("cp.async.commit_group;\n");

    for (int kt = 0; kt < ntiles; kt++) {
        int cur = kt & 1;
        if (kt + 1 < ntiles) {
            load_stage(cur ^ 1, (kt + 1) * TBK);
            asm volatile("cp.async.commit_group;\n");
            asm volatile("cp.async.wait_group 1;\n");
        } else {
            asm volatile("cp.async.wait_group 0;\n");
        }
        __syncthreads();

        const float* Af = As[cur];
        const float* Bf = Bs[cur];
        #pragma unroll
        for (int ks = 0; ks < 2; ks++) {
            const int k0 = ks * 8;
            unsigned a[2][4], b[4][2];
            #pragma unroll
            for (int mi = 0; mi < 2; mi++) {
                int m = wm + mi * 16;
                a[mi][0] = to_tf32_bits(Af[(m + g)     * ASTR + k0 + t4]);
                a[mi][1] = to_tf32_bits(Af[(m + g + 8) * ASTR + k0 + t4]);
                a[mi][2] = to_tf32_bits(Af[(m + g)     * ASTR + k0 + t4 + 4]);
                a[mi][3] = to_tf32_bits(Af[(m + g + 8) * ASTR + k0 + t4 + 4]);
            }
            #pragma unroll
            for (int ni = 0; ni < 4; ni++) {
                int n = wn + ni * 8 + g;
                b[ni][0] = to_tf32_bits(Bf[(k0 + t4)     * BSTR + n]);
                b[ni][1] = to_tf32_bits(Bf[(k0 + t4 + 4) * BSTR + n]);
            }
            #pragma unroll
            for (int mi = 0; mi < 2; mi++)
                #pragma unroll
                for (int ni = 0; ni < 4; ni++) {
                    asm volatile(
                        "mma.sync.aligned.m16n8k8.row.col.f32.tf32.tf32.f32 "
                        "{%0,%1,%2,%3}, {%4,%5,%6,%7}, {%8,%9}, {%0,%1,%2,%3};\n"
                        : "+f"(acc[mi][ni][0]), "+f"(acc[mi][ni][1]),
                          "+f"(acc[mi][ni][2]), "+f"(acc[mi][ni][3])
                        : "r"(a[mi][0]), "r"(a[mi][1]), "r"(a[mi][2]), "r"(a[mi][3]),
                          "r"(b[ni][0]), "r"(b[ni][1]));
                }
        }
        __syncthreads();
    }

    // ---- epilogue ----
    #pragma unroll
    for (int mi = 0; mi < 2; mi++) {
        #pragma unroll
        for (int ni = 0; ni < 4; ni++) {
            int r0 = row0 + wm + mi * 16 + g;
            int c  = col0 + wn + ni * 8 + 2 * t4;
            if (c + 1 < Nc) {
                *(float2*)&C[(long)r0 * ldc + c] =
                    make_float2(acc[mi][ni][0], acc[mi][ni][1]);
                *(float2*)&C[(long)(r0 + 8) * ldc + c] =
                    make_float2(acc[mi][ni][2], acc[mi][ni][3]);
            } else if (c < Nc) {
                C[(long)r0 * ldc + c]       = acc[mi][ni][0];
                C[(long)(r0 + 8) * ldc + c] = acc[mi][ni][2];
            }
        }
    }
}

// ---------------- zero accumulators (ssum + agg), float4 ----------------
__global__ void zero_accum_kernel()
{
    int i = blockIdx.x * blockDim.x + threadIdx.x;   // 0 .. NN*DD/4
    if (i < NN * DD / 4) ((float4*)g_agg)[i] = make_float4(0.f, 0.f, 0.f, 0.f);
    if (i < NN * HH / 4) ((float4*)g_ssum)[i] = make_float4(0.f, 0.f, 0.f, 0.f);
}

// ---------------- fused edge pass: cross attention ----------------
// scores (exp) + unnormalized weighted-value aggregation in one pass
__global__ void edge_cross_fused(
    const float* __restrict__ q, const float* __restrict__ kv,
    const int* __restrict__ eidx, int E, float scale)
{
    int warp = (blockIdx.x * blockDim.x + threadIdx.x) >> 5;
    int lane = threadIdx.x & 31;
    if (warp >= E) return;
    int src = eidx[warp];
    int dst = eidx[E + warp];
    int h  = lane >> 2;
    int d0 = lane & 3;
    const float* qr  = q  + (long)dst * DD    + h * HDIM;
    const float* kvr = kv + (long)src * 2*DD  + h * 2*HDIM;
    float acc = 0.f;
    #pragma unroll
    for (int i = 0; i < 8; i++) {
        int d = d0 + i * 4;
        acc = fmaf(qr[d], kvr[2 * d], acc);
    }
    acc += __shfl_down_sync(0xffffffffu, acc, 2);
    acc += __shfl_down_sync(0xffffffffu, acc, 1);
    float sc = expf(acc * scale);           // valid on lanes with d0==0
    if (d0 == 0) atomicAdd(&g_ssum[(long)dst * HH + h], sc);
    const float* vb = kv + (long)src * 2*DD + 2 * lane + 1;
    float* ab = g_agg + (long)dst * DD + lane;
    #pragma unroll
    for (int hh = 0; hh < HH; hh++) {
        float w = __shfl_sync(0xffffffffu, sc, hh * 4);
        atomicAdd(ab + hh * HDIM, w * vb[hh * 2 * HDIM]);
    }
}

// ---------------- fused edge pass: self attention ----------------
__global__ void edge_self_fused(
    const float* __restrict__ qkv, const float* __restrict__ attr,
    const int* __restrict__ eidx, int E)
{
    int warp = (blockIdx.x * blockDim.x + threadIdx.x) >> 5;
    int lane = threadIdx.x & 31;
    if (warp >= E) return;
    int src = eidx[warp];
    int dst = eidx[E + warp];
    int h  = lane >> 2;
    int d0 = lane & 3;
    const float* qr = qkv + (long)dst * 3*DD + h * 3*HDIM;
    const float* kr = qkv + (long)src * 3*DD + h * 3*HDIM;
    const float* ar = attr + (long)warp * DD + h * HDIM;
    float acc = 0.f;
    #pragma unroll
    for (int i = 0; i < 8; i++) {
        int d = d0 + i * 4;
        acc = fmaf(qr[3 * d] * kr[3 * d + 1], ar[d], acc);
    }
    acc += __shfl_down_sync(0xffffffffu, acc, 2);
    acc += __shfl_down_sync(0xffffffffu, acc, 1);
    float sc = expf(acc);
    if (d0 == 0) atomicAdd(&g_ssum[(long)dst * HH + h], sc);
    const float* vb = qkv + (long)src * 3*DD + 3 * lane + 2;
    float* ab = g_agg + (long)dst * DD + lane;
    #pragma unroll
    for (int hh = 0; hh < HH; hh++) {
        float w = __shfl_sync(0xffffffffu, sc, hh * 4);
        atomicAdd(ab + hh * HDIM, w * vb[hh * 3 * HDIM]);
    }
}

// ---------------- normalize aggregation by softmax denominator ----------
__global__ void normalize_agg_kernel()
{
    int i = blockIdx.x * blockDim.x + threadIdx.x;   // NN*DD
    int r = i >> 8, c = i & 255;
    float s = g_ssum[r * HH + (c >> 5)];
    g_agg[i] = (s > 0.f) ? g_agg[i] / s : 0.f;       // guard: edgeless dst nodes
}

// ---------------- residual + RMS norm ----------------
__global__ void add_rmsnorm_kernel(
    const float* __restrict__ a, const float* __restrict__ b,
    const float* __restrict__ g, float* __restrict__ out, int N)
{
    int row = blockIdx.x;
    int t = threadIdx.x;
    if (row >= N) return;
    float x = a[(long)row * DD + t] + b[(long)row * DD + t];
    float ss = x * x;
    #pragma unroll
    for (int o = 16; o > 0; o >>= 1) ss += __shfl_xor_sync(0xffffffffu, ss, o);
    __shared__ float sh[8];
    __shared__ float stot;
    if ((t & 31) == 0) sh[t >> 5] = ss;
    __syncthreads();
    if (t == 0) {
        float s = 0.f;
        #pragma unroll
        for (int i = 0; i < 8; i++) s += sh[i];
        stot = s;
    }
    __syncthreads();
    float norm = sqrtf(stot * (1.0f / DD));
    float denom = fmaxf(norm, 1e-8f);
    out[(long)row * DD + t] = x / denom * g[t];
}

// ---------------- SwiGLU elementwise (over padded buffers) ----------
__global__ void swiglu_mul_kernel(float* __restrict__ h1,
                                  const float* __restrict__ h2, long n)
{
    long i = (long)blockIdx.x * blockDim.x + threadIdx.x;
    if (i >= n) return;
    float h = h1[i];
    float sig = 1.0f / (1.0f + expf(-h));
    h1[i] = h * sig * h2[i];
}

// ---------------- host launcher ----------------
static inline void run_gemm(const float* A, int lda, const float* B, int ldb,
                            float* C, int ldc, int M, int Nc, int K)
{
    dim3 grid((Nc + TBN - 1) / TBN, (M + TBM - 1) / TBM);
    tf32_gemm_pipe<<<grid, 256>>>(A, lda, B, ldb, C, ldc, M, Nc, K);
}

extern "C" void kernel_launch(void* const* d_in, const int* in_sizes, int n_in,
                              void* d_out, int out_size)
{
    const float* root   = (const float*)d_in[0];
    const float* node   = (const float*)d_in[1];
    const float* fringe = (const float*)d_in[2];
    const int* ntr_idx  = (const int*)d_in[3];
    const int* rtr_idx  = (const int*)d_in[4];
    const int* rtf_idx  = (const int*)d_in[5];
    const float* edge_attr = (const float*)d_in[6];
    const float* ntr_wq  = (const float*)d_in[7];
    const float* ntr_wkv = (const float*)d_in[8];
    const float* ntr_wout= (const float*)d_in[9];
    const float* ntr_g   = (const float*)d_in[10];
    const float* rtr_wqkv= (const float*)d_in[11];
    const float* rtr_wout= (const float*)d_in[12];
    const float* rtr_g   = (const float*)d_in[13];
    const float* ffn_win = (const float*)d_in[14];
    const float* ffn_v   = (const float*)d_in[15];
    const float* ffn_wout= (const float*)d_in[16];
    const float* ffn_g   = (const float*)d_in[17];
    const float* rtf_wq  = (const float*)d_in[18];
    const float* rtf_wkv = (const float*)d_in[19];
    const float* rtf_wout= (const float*)d_in[20];
    float* out = (float*)d_out;

    const int N = in_sizes[0] / DD;     // 16384
    const int E = in_sizes[3] / 2;      // 131072
    const int I = in_sizes[14] / DD;    // 682
    const float scale = 0.17677669529663689f;  // 1/sqrt(32)

    float *p_q, *p_kv, *p_qkv, *p_agg, *p_tmp, *p_x1, *p_x2, *p_h1, *p_h2;
    cudaGetSymbolAddress((void**)&p_q,   g_q);
    cudaGetSymbolAddress((void**)&p_kv,  g_kv);
    cudaGetSymbolAddress((void**)&p_qkv, g_qkv);
    cudaGetSymbolAddress((void**)&p_agg, g_agg);
    cudaGetSymbolAddress((void**)&p_tmp, g_tmp);
    cudaGetSymbolAddress((void**)&p_x1,  g_x1);
    cudaGetSymbolAddress((void**)&p_x2,  g_x2);
    cudaGetSymbolAddress((void**)&p_h1,  g_h1);
    cudaGetSymbolAddress((void**)&p_h2,  g_h2);

    const int edge_blocks = (E * 32 + 255) / 256;
    const int zero_blocks = (N * DD / 4 + 255) / 256;
    const int norm_blocks = (N * DD + 255) / 256;

    // ===== Stage 1: nodes_to_root CrossMHA + residual + RMSNorm -> x1 =====
    zero_accum_kernel<<<zero_blocks, 256>>>();
    run_gemm(root, DD, ntr_wq,  DD,     p_q,  DD,     N, DD,     DD);
    run_gemm(node, DD, ntr_wkv, 2 * DD, p_kv, 2 * DD, N, 2 * DD, DD);
    edge_cross_fused<<<edge_blocks, 256>>>(p_q, p_kv, ntr_idx, E, scale);
    normalize_agg_kernel<<<norm_blocks, 256>>>();
    run_gemm(p_agg, DD, ntr_wout, DD, p_tmp, DD, N, DD, DD);
    add_rmsnorm_kernel<<<N, 256>>>(root, p_tmp, ntr_g, p_x1, N);

    // ===== Stage 2: roots_to_root SelfMHA + residual + RMSNorm -> x2 =====
    zero_accum_kernel<<<zero_blocks, 256>>>();
    run_gemm(p_x1, DD, rtr_wqkv, 3 * DD, p_qkv, 3 * DD, N, 3 * DD, DD);
    edge_self_fused<<<edge_blocks, 256>>>(p_qkv, edge_attr, rtr_idx, E);
    normalize_agg_kernel<<<norm_blocks, 256>>>();
    run_gemm(p_agg, DD, rtr_wout, DD, p_tmp, DD, N, DD, DD);
    add_rmsnorm_kernel<<<N, 256>>>(p_x1, p_tmp, rtr_g, p_x2, N);

    // ===== Stage 3: SwiGLU FFN + residual + RMSNorm -> out[0:N*D) =====
    run_gemm(root, DD, ffn_win, I, p_h1, ILD, N, I, DD);
    run_gemm(root, DD, ffn_v,   I, p_h2, ILD, N, I, DD);
    {
        long nel = (long)N * ILD;
        swiglu_mul_kernel<<<(int)((nel + 255) / 256), 256>>>(p_h1, p_h2, nel);
    }
    run_gemm(p_h1, ILD, ffn_wout, DD, p_tmp, DD, N, DD, I);
    add_rmsnorm_kernel<<<N, 256>>>(p_tmp, p_x2, ffn_g, out, N);

    // ===== Stage 4: root_to_fringe CrossMHA -> out[N*D : 2*N*D) =====
    zero_accum_kernel<<<zero_blocks, 256>>>();
    run_gemm(fringe, DD, rtf_wq,  DD,     p_q,  DD,     N, DD,     DD);
    run_gemm(root,   DD, rtf_wkv, 2 * DD, p_kv, 2 * DD, N, 2 * DD, DD);
    edge_cross_fused<<<edge_blocks, 256>>>(p_q, p_kv, rtf_idx, E, scale);
    normalize_agg_kernel<<<norm_blocks, 256>>>();
    run_gemm(p_agg, DD, rtf_wout, DD, out + (long)N * DD, DD, N, DD, DD);
}